// round 1
// baseline (speedup 1.0000x reference)
#include <cuda_runtime.h>

#define S_LEN 2048
#define DM    1024
#define NH    16
#define HS    64
#define NBATCH 2

// Scratch (allocation-free rule: __device__ globals)
__device__ float g_Q[(size_t)NBATCH * NH * S_LEN * HS];
__device__ float g_K[(size_t)NBATCH * NH * S_LEN * HS];
__device__ float g_V[(size_t)NBATCH * NH * S_LEN * HS];
__device__ float g_attn[(size_t)NBATCH * S_LEN * DM];

// ---------------------------------------------------------------------------
// K1: per-head QKV projection.  out[b,h,s,:] = X[b,s,:] @ W[h] + bias[h]
// grid: (4096/64 row-tiles, 16 heads, 3 {q,k,v}), block 256 (16x16, 4x4 micro)
// ---------------------------------------------------------------------------
__global__ __launch_bounds__(256) void qkv_kernel(
    const float* __restrict__ Xq, const float* __restrict__ Xk, const float* __restrict__ Xv,
    const float* __restrict__ Wq, const float* __restrict__ Wk, const float* __restrict__ Wv,
    const float* __restrict__ bq, const float* __restrict__ bk, const float* __restrict__ bv)
{
    const float* X; const float* W; const float* bias; float* out;
    int z = blockIdx.z;
    if (z == 0)      { X = Xq; W = Wq; bias = bq; out = g_Q; }
    else if (z == 1) { X = Xk; W = Wk; bias = bk; out = g_K; }
    else             { X = Xv; W = Wv; bias = bv; out = g_V; }

    int h  = blockIdx.y;
    int r0 = blockIdx.x * 64;         // global row in [0,4096)
    int tid = threadIdx.x;
    int tx = tid & 15, ty = tid >> 4;

    __shared__ float As[16][64];
    __shared__ float Bs[16][64];

    float acc[4][4] = {};
    for (int k0 = 0; k0 < DM; k0 += 16) {
        // X tile 64x16 -> As[kd][m] (transposed)
        {
            int m  = tid >> 2;
            int kd = (tid & 3) * 4;
            float4 v = *(const float4*)(X + (size_t)(r0 + m) * DM + k0 + kd);
            As[kd + 0][m] = v.x; As[kd + 1][m] = v.y;
            As[kd + 2][m] = v.z; As[kd + 3][m] = v.w;
        }
        // W tile 16x64 -> Bs[kd][n]
        {
            int kd = tid >> 4;
            int n4 = (tid & 15) * 4;
            float4 v = *(const float4*)(W + ((size_t)h * DM + k0 + kd) * HS + n4);
            *(float4*)&Bs[kd][n4] = v;
        }
        __syncthreads();
        #pragma unroll
        for (int kk = 0; kk < 16; kk++) {
            float a[4], bb[4];
            #pragma unroll
            for (int i = 0; i < 4; i++) a[i]  = As[kk][ty * 4 + i];
            #pragma unroll
            for (int j = 0; j < 4; j++) bb[j] = Bs[kk][tx * 4 + j];
            #pragma unroll
            for (int i = 0; i < 4; i++)
                #pragma unroll
                for (int j = 0; j < 4; j++)
                    acc[i][j] += a[i] * bb[j];
        }
        __syncthreads();
    }

    int b = r0 / S_LEN;
    int s = r0 % S_LEN;
    #pragma unroll
    for (int i = 0; i < 4; i++) {
        size_t base = ((size_t)(b * NH + h) * S_LEN + (s + ty * 4 + i)) * HS;
        #pragma unroll
        for (int j = 0; j < 4; j++) {
            int n = tx * 4 + j;
            out[base + n] = acc[i][j] + bias[h * HS + n];
        }
    }
}

// ---------------------------------------------------------------------------
// K2: flash attention per (b, h, q-tile of 64 rows).
// Dynamic smem: Qs[64][65] | Ks[64][65] (reused as P) | Vs[64][64]
// ---------------------------------------------------------------------------
#define FLASH_SMEM_BYTES ((2 * 64 * 65 + 64 * 64) * 4)

extern __shared__ float fl_sm[];

__global__ __launch_bounds__(256) void flash_kernel()
{
    float* Qs = fl_sm;                // [64][65]
    float* Ks = fl_sm + 64 * 65;      // [64][65]  (later holds P)
    float* Vs = fl_sm + 2 * 64 * 65;  // [64][64]

    int q0 = blockIdx.x * 64;
    int h  = blockIdx.y;
    int b  = blockIdx.z;
    int tid = threadIdx.x;
    int tx = tid & 15, ty = tid >> 4;

    size_t head_base = (size_t)(b * NH + h) * S_LEN * HS;
    const float scale = 0.125f;  // 1/sqrt(64)

    // load Q tile (pre-scaled)
    for (int idx = tid; idx < 1024; idx += 256) {
        int m = idx >> 4;
        int c = (idx & 15) * 4;
        float4 v = *(const float4*)(g_Q + head_base + (size_t)(q0 + m) * HS + c);
        Qs[m * 65 + c + 0] = v.x * scale;
        Qs[m * 65 + c + 1] = v.y * scale;
        Qs[m * 65 + c + 2] = v.z * scale;
        Qs[m * 65 + c + 3] = v.w * scale;
    }

    float m_i[4], l_i[4], o[4][4] = {};
    #pragma unroll
    for (int i = 0; i < 4; i++) { m_i[i] = -1e30f; l_i[i] = 0.f; }

    for (int j0 = 0; j0 < S_LEN; j0 += 64) {
        __syncthreads();  // previous PV done reading Ks/Vs; Qs ready (first iter)
        for (int idx = tid; idx < 1024; idx += 256) {
            int m = idx >> 4;
            int c = (idx & 15) * 4;
            float4 kv = *(const float4*)(g_K + head_base + (size_t)(j0 + m) * HS + c);
            Ks[m * 65 + c + 0] = kv.x; Ks[m * 65 + c + 1] = kv.y;
            Ks[m * 65 + c + 2] = kv.z; Ks[m * 65 + c + 3] = kv.w;
            float4 vv = *(const float4*)(g_V + head_base + (size_t)(j0 + m) * HS + c);
            *(float4*)&Vs[m * 64 + c] = vv;
        }
        __syncthreads();

        // S = Q K^T (64x64 tile, 4x4 per thread)
        float acc[4][4] = {};
        #pragma unroll 4
        for (int kk = 0; kk < 64; kk++) {
            float a[4], bb[4];
            #pragma unroll
            for (int i = 0; i < 4; i++) a[i]  = Qs[(ty * 4 + i) * 65 + kk];
            #pragma unroll
            for (int j = 0; j < 4; j++) bb[j] = Ks[(tx * 4 + j) * 65 + kk];
            #pragma unroll
            for (int i = 0; i < 4; i++)
                #pragma unroll
                for (int j = 0; j < 4; j++)
                    acc[i][j] += a[i] * bb[j];
        }

        // online softmax (rows owned by 16 lanes sharing ty; lanes differ in tx)
        #pragma unroll
        for (int i = 0; i < 4; i++) {
            float rm = acc[i][0];
            #pragma unroll
            for (int j = 1; j < 4; j++) rm = fmaxf(rm, acc[i][j]);
            #pragma unroll
            for (int off = 8; off > 0; off >>= 1)
                rm = fmaxf(rm, __shfl_xor_sync(0xffffffffu, rm, off));
            float nm = fmaxf(m_i[i], rm);
            float sum = 0.f;
            #pragma unroll
            for (int j = 0; j < 4; j++) {
                acc[i][j] = __expf(acc[i][j] - nm);
                sum += acc[i][j];
            }
            #pragma unroll
            for (int off = 8; off > 0; off >>= 1)
                sum += __shfl_xor_sync(0xffffffffu, sum, off);
            float corr = __expf(m_i[i] - nm);
            l_i[i] = l_i[i] * corr + sum;
            m_i[i] = nm;
            #pragma unroll
            for (int j = 0; j < 4; j++) o[i][j] *= corr;
        }

        __syncthreads();  // all done reading Ks as K
        #pragma unroll
        for (int i = 0; i < 4; i++)
            #pragma unroll
            for (int j = 0; j < 4; j++)
                Ks[(ty * 4 + i) * 65 + tx * 4 + j] = acc[i][j];
        __syncthreads();  // P visible

        // O += P @ V
        #pragma unroll 4
        for (int kk = 0; kk < 64; kk++) {
            float a[4], vv[4];
            #pragma unroll
            for (int i = 0; i < 4; i++) a[i]  = Ks[(ty * 4 + i) * 65 + kk];
            #pragma unroll
            for (int j = 0; j < 4; j++) vv[j] = Vs[kk * 64 + tx * 4 + j];
            #pragma unroll
            for (int i = 0; i < 4; i++)
                #pragma unroll
                for (int j = 0; j < 4; j++)
                    o[i][j] += a[i] * vv[j];
        }
    }

    // epilogue: normalize + write to [b, s, h*HS + k] layout
    #pragma unroll
    for (int i = 0; i < 4; i++) {
        float inv = 1.0f / l_i[i];
        size_t base = ((size_t)b * S_LEN + q0 + ty * 4 + i) * DM + h * HS;
        #pragma unroll
        for (int j = 0; j < 4; j++)
            g_attn[base + tx * 4 + j] = o[i][j] * inv;
    }
}

// ---------------------------------------------------------------------------
// K3: output projection  out[r,n] = sum_d attn[r,d] * Wo[n,d] + bo[n]
// grid: (4096/64, 1024/64), block 256
// ---------------------------------------------------------------------------
__global__ __launch_bounds__(256) void oproj_kernel(
    const float* __restrict__ Wo, const float* __restrict__ bo,
    float* __restrict__ out)
{
    int r0 = blockIdx.x * 64;
    int n0 = blockIdx.y * 64;
    int tid = threadIdx.x;
    int tx = tid & 15, ty = tid >> 4;

    __shared__ float As[16][64];
    __shared__ float Bs[16][64];

    float acc[4][4] = {};
    for (int k0 = 0; k0 < DM; k0 += 16) {
        {
            int m  = tid >> 2;
            int kd = (tid & 3) * 4;
            float4 v = *(const float4*)(g_attn + (size_t)(r0 + m) * DM + k0 + kd);
            As[kd + 0][m] = v.x; As[kd + 1][m] = v.y;
            As[kd + 2][m] = v.z; As[kd + 3][m] = v.w;
        }
        {
            int n  = tid >> 2;
            int kd = (tid & 3) * 4;
            float4 v = *(const float4*)(Wo + (size_t)(n0 + n) * DM + k0 + kd);
            Bs[kd + 0][n] = v.x; Bs[kd + 1][n] = v.y;
            Bs[kd + 2][n] = v.z; Bs[kd + 3][n] = v.w;
        }
        __syncthreads();
        #pragma unroll
        for (int kk = 0; kk < 16; kk++) {
            float a[4], bb[4];
            #pragma unroll
            for (int i = 0; i < 4; i++) a[i]  = As[kk][ty * 4 + i];
            #pragma unroll
            for (int j = 0; j < 4; j++) bb[j] = Bs[kk][tx * 4 + j];
            #pragma unroll
            for (int i = 0; i < 4; i++)
                #pragma unroll
                for (int j = 0; j < 4; j++)
                    acc[i][j] += a[i] * bb[j];
        }
        __syncthreads();
    }

    #pragma unroll
    for (int i = 0; i < 4; i++) {
        size_t base = (size_t)(r0 + ty * 4 + i) * DM + n0;
        #pragma unroll
        for (int j = 0; j < 4; j++)
            out[base + tx * 4 + j] = acc[i][j] + bo[n0 + tx * 4 + j];
    }
}

// ---------------------------------------------------------------------------
extern "C" void kernel_launch(void* const* d_in, const int* in_sizes, int n_in,
                              void* d_out, int out_size)
{
    const float* query  = (const float*)d_in[0];
    const float* key_in = (const float*)d_in[1];
    const float* value  = (const float*)d_in[2];
    const float* Wq     = (const float*)d_in[3];
    const float* Wk     = (const float*)d_in[4];
    const float* Wv     = (const float*)d_in[5];
    const float* bq     = (const float*)d_in[6];
    const float* bk     = (const float*)d_in[7];
    const float* bv     = (const float*)d_in[8];
    const float* Wo     = (const float*)d_in[9];
    const float* bo     = (const float*)d_in[10];
    float* out = (float*)d_out;

    cudaFuncSetAttribute(flash_kernel,
                         cudaFuncAttributeMaxDynamicSharedMemorySize,
                         FLASH_SMEM_BYTES);

    qkv_kernel<<<dim3(64, 16, 3), 256>>>(query, key_in, value,
                                         Wq, Wk, Wv, bq, bk, bv);
    flash_kernel<<<dim3(S_LEN / 64, NH, NBATCH), 256, FLASH_SMEM_BYTES>>>();
    oproj_kernel<<<dim3(64, 16), 256>>>(Wo, bo, out);
}

// round 3
// speedup vs baseline: 3.6700x; 3.6700x over previous
#include <cuda_runtime.h>
#include <cuda_fp16.h>
#include <cstdint>

#define S_LEN 2048
#define DM    1024
#define NH    16
#define HS    64
#define NBATCH 2

// ---------------------------------------------------------------------------
// Scratch (allocation-free rule: __device__ globals)
// ---------------------------------------------------------------------------
__device__ float g_Q[(size_t)NBATCH * NH * S_LEN * HS];
__device__ float g_K[(size_t)NBATCH * NH * S_LEN * HS];
__device__ float g_V[(size_t)NBATCH * NH * S_LEN * HS];
__device__ float g_attn[(size_t)NBATCH * S_LEN * DM];
__device__ float g_Wt[(size_t)3 * NH * HS * DM];   // K-major transposed weights

// ---------------------------------------------------------------------------
// mma.sync helpers (base PTX, works at target sm_103)
// ---------------------------------------------------------------------------
__device__ __forceinline__ uint32_t f32_tf32(float f) {
    uint32_t r;
    asm("cvt.rna.tf32.f32 %0, %1;" : "=r"(r) : "f"(f));
    return r;
}

__device__ __forceinline__ void mma_tf32(float d[4], const uint32_t a[4],
                                         const uint32_t b[2], const float c[4]) {
    asm volatile(
        "mma.sync.aligned.m16n8k8.row.col.f32.tf32.tf32.f32 "
        "{%0,%1,%2,%3},{%4,%5,%6,%7},{%8,%9},{%10,%11,%12,%13};"
        : "=f"(d[0]), "=f"(d[1]), "=f"(d[2]), "=f"(d[3])
        : "r"(a[0]), "r"(a[1]), "r"(a[2]), "r"(a[3]),
          "r"(b[0]), "r"(b[1]),
          "f"(c[0]), "f"(c[1]), "f"(c[2]), "f"(c[3]));
}

__device__ __forceinline__ void mma_f16(float d[4], const uint32_t a[4],
                                        const uint32_t b[2], const float c[4]) {
    asm volatile(
        "mma.sync.aligned.m16n8k16.row.col.f32.f16.f16.f32 "
        "{%0,%1,%2,%3},{%4,%5,%6,%7},{%8,%9},{%10,%11,%12,%13};"
        : "=f"(d[0]), "=f"(d[1]), "=f"(d[2]), "=f"(d[3])
        : "r"(a[0]), "r"(a[1]), "r"(a[2]), "r"(a[3]),
          "r"(b[0]), "r"(b[1]),
          "f"(c[0]), "f"(c[1]), "f"(c[2]), "f"(c[3]));
}

__device__ __forceinline__ uint32_t pack_h2(float lo, float hi) {
    __half2 h = __floats2half2_rn(lo, hi);
    return *(uint32_t*)&h;
}

// exp on the FMA pipe only (no MUFU): x <= 0 expected.
__device__ __forceinline__ float fast_exp(float x) {
    x = fmaxf(x, -80.0f);
    float t = fmaf(x, 1.4426950408889634f, 12582912.0f);  // magic-round
    float n = t - 12582912.0f;                            // round(x*log2e)
    float f = fmaf(x, 1.4426950408889634f, -n);           // frac in [-0.5,0.5]
    float p = 1.3333558146e-3f;
    p = fmaf(p, f, 9.6181291076e-3f);
    p = fmaf(p, f, 5.5504108664e-2f);
    p = fmaf(p, f, 2.4022650696e-1f);
    p = fmaf(p, f, 6.9314718056e-1f);
    p = fmaf(p, f, 1.0f);
    int ni = __float_as_int(t) - 0x4B400000;              // n as int
    return __int_as_float(__float_as_int(p) + (ni << 23)); // p * 2^n
}

// ---------------------------------------------------------------------------
// Shared GEMM core: 128x128 tile, K=1024, tf32 mma, 8 warps (2m x 4n),
// warp tile 64x32. acc[mi][ni][4].
// ---------------------------------------------------------------------------
#define GP 36   // padded floats per 32-float smem row

__device__ __forceinline__ void gemm_tile_tf32(
    const float* __restrict__ A, const float* __restrict__ B,
    float* As, float* Bs, float acc[4][4][4])
{
    int tid = threadIdx.x, lane = tid & 31, wid = tid >> 5;
    int wm = wid & 1, wn = wid >> 1;
    int lr = lane >> 2, lc = lane & 3;
    uint32_t* Au = (uint32_t*)As;
    uint32_t* Bu = (uint32_t*)Bs;

    for (int kc = 0; kc < DM; kc += 32) {
        __syncthreads();
        #pragma unroll
        for (int t = 0; t < 4; t++) {
            int idx = tid + t * 256;
            int m = idx >> 3, c = (idx & 7) * 4;
            float4 va = *(const float4*)(A + (size_t)m * DM + kc + c);
            uint32_t* pa = Au + m * GP + c;
            pa[0] = f32_tf32(va.x); pa[1] = f32_tf32(va.y);
            pa[2] = f32_tf32(va.z); pa[3] = f32_tf32(va.w);
            float4 vb = *(const float4*)(B + (size_t)m * DM + kc + c);
            uint32_t* pb = Bu + m * GP + c;
            pb[0] = f32_tf32(vb.x); pb[1] = f32_tf32(vb.y);
            pb[2] = f32_tf32(vb.z); pb[3] = f32_tf32(vb.w);
        }
        __syncthreads();
        #pragma unroll
        for (int ks = 0; ks < 4; ks++) {
            int k0 = ks * 8;
            uint32_t af[4][4], bf[4][2];
            #pragma unroll
            for (int mi = 0; mi < 4; mi++) {
                int m0 = wm * 64 + mi * 16;
                af[mi][0] = Au[(m0 +     lr) * GP + k0 +     lc];
                af[mi][1] = Au[(m0 + 8 + lr) * GP + k0 +     lc];
                af[mi][2] = Au[(m0 +     lr) * GP + k0 + 4 + lc];
                af[mi][3] = Au[(m0 + 8 + lr) * GP + k0 + 4 + lc];
            }
            #pragma unroll
            for (int ni = 0; ni < 4; ni++) {
                int n0 = wn * 32 + ni * 8;
                bf[ni][0] = Bu[(n0 + lr) * GP + k0 +     lc];
                bf[ni][1] = Bu[(n0 + lr) * GP + k0 + 4 + lc];
            }
            #pragma unroll
            for (int mi = 0; mi < 4; mi++)
                #pragma unroll
                for (int ni = 0; ni < 4; ni++)
                    mma_tf32(acc[mi][ni], af[mi], bf[ni], acc[mi][ni]);
        }
    }
}

// ---------------------------------------------------------------------------
// K0: transpose W[h][d][n] -> g_Wt[z][h][n][d]
// ---------------------------------------------------------------------------
__global__ __launch_bounds__(256) void transpose_w_kernel(
    const float* __restrict__ Wq, const float* __restrict__ Wk,
    const float* __restrict__ Wv)
{
    int z = blockIdx.z;
    const float* W = (z == 0) ? Wq : (z == 1) ? Wk : Wv;
    int h  = blockIdx.y;
    int k0 = blockIdx.x * 64;
    __shared__ float t[64][65];
    int tid = threadIdx.x;
    for (int i = tid; i < 4096; i += 256) {
        int r = i >> 6, c = i & 63;
        t[r][c] = W[((size_t)h * DM + k0 + r) * HS + c];
    }
    __syncthreads();
    float* outp = g_Wt + ((size_t)z * NH + h) * HS * DM;
    for (int i = tid; i < 4096; i += 256) {
        int n = i >> 6, kk = i & 63;
        outp[(size_t)n * DM + k0 + kk] = t[kk][n];
    }
}

// ---------------------------------------------------------------------------
// K1: QKV projection. grid (32 rowtiles, 8 coltiles(=2 heads), 3)
// ---------------------------------------------------------------------------
__global__ __launch_bounds__(256) void qkv_mma_kernel(
    const float* __restrict__ Xq, const float* __restrict__ Xk,
    const float* __restrict__ Xv,
    const float* __restrict__ bq, const float* __restrict__ bk,
    const float* __restrict__ bv)
{
    __shared__ float As[128 * GP];
    __shared__ float Bs[128 * GP];
    int z = blockIdx.z;
    const float* X; const float* bias; float* outp;
    if (z == 0)      { X = Xq; bias = bq; outp = g_Q; }
    else if (z == 1) { X = Xk; bias = bk; outp = g_K; }
    else             { X = Xv; bias = bv; outp = g_V; }

    int r0 = blockIdx.x * 128;
    int n0 = blockIdx.y * 128;
    const float* A = X + (size_t)r0 * DM;
    const float* B = g_Wt + ((size_t)z * 1024 + n0) * DM;

    float acc[4][4][4] = {};
    gemm_tile_tf32(A, B, As, Bs, acc);

    int lane = threadIdx.x & 31, wid = threadIdx.x >> 5;
    int wm = wid & 1, wn = wid >> 1, lr = lane >> 2, lc = lane & 3;
    #pragma unroll
    for (int mi = 0; mi < 4; mi++) {
        int gr = r0 + wm * 64 + mi * 16 + lr;
        int bb = gr >> 11, ss = gr & (S_LEN - 1);
        #pragma unroll
        for (int ni = 0; ni < 4; ni++) {
            int gn = n0 + wn * 32 + ni * 8 + 2 * lc;
            int hh = gn >> 6, hc = gn & 63;
            float bv0 = bias[hh * 64 + hc];
            float bv1 = bias[hh * 64 + hc + 1];
            float* dst = outp + ((size_t)(bb * NH + hh) * S_LEN + ss) * HS + hc;
            float2 v0 = { acc[mi][ni][0] + bv0, acc[mi][ni][1] + bv1 };
            float2 v1 = { acc[mi][ni][2] + bv0, acc[mi][ni][3] + bv1 };
            *(float2*)dst = v0;
            *(float2*)(dst + 8 * HS) = v1;
        }
    }
}

// ---------------------------------------------------------------------------
// K3: output projection. grid (32 rowtiles, 8 coltiles)
// ---------------------------------------------------------------------------
__global__ __launch_bounds__(256) void oproj_mma_kernel(
    const float* __restrict__ Wo, const float* __restrict__ bo,
    float* __restrict__ out)
{
    __shared__ float As[128 * GP];
    __shared__ float Bs[128 * GP];
    int r0 = blockIdx.x * 128;
    int n0 = blockIdx.y * 128;
    const float* A = g_attn + (size_t)r0 * DM;
    const float* B = Wo + (size_t)n0 * DM;

    float acc[4][4][4] = {};
    gemm_tile_tf32(A, B, As, Bs, acc);

    int lane = threadIdx.x & 31, wid = threadIdx.x >> 5;
    int wm = wid & 1, wn = wid >> 1, lr = lane >> 2, lc = lane & 3;
    #pragma unroll
    for (int mi = 0; mi < 4; mi++) {
        int gr = r0 + wm * 64 + mi * 16 + lr;
        #pragma unroll
        for (int ni = 0; ni < 4; ni++) {
            int gn = n0 + wn * 32 + ni * 8 + 2 * lc;
            float bv0 = bo[gn], bv1 = bo[gn + 1];
            float* dst = out + (size_t)gr * DM + gn;
            float2 v0 = { acc[mi][ni][0] + bv0, acc[mi][ni][1] + bv1 };
            float2 v1 = { acc[mi][ni][2] + bv0, acc[mi][ni][3] + bv1 };
            *(float2*)dst = v0;
            *(float2*)(dst + 8 * DM) = v1;
        }
    }
}

// ---------------------------------------------------------------------------
// K2: flash attention, fp16 mma. q-tile 128, 8 warps, warp = 16 q-rows x all
// 128 kv cols. P stays in registers (f16 C->A fragment layout identity).
// Dyn smem: Qs[128][72]h | Ks[128][72]h | Vt[64][136]h  = 54272 B
// ---------------------------------------------------------------------------
#define QK_PAD 72     // halfs per row (64 + 8)
#define VT_PAD 136    // halfs per row (128 + 8)
#define FLASH_SMEM ((128 * QK_PAD * 2 + 64 * VT_PAD) * 2)

extern __shared__ __align__(16) char dynsm[];

__global__ __launch_bounds__(256) void flash_mma_kernel()
{
    __half* Qs = (__half*)dynsm;
    __half* Ks = Qs + 128 * QK_PAD;
    __half* Vt = Ks + 128 * QK_PAD;
    const uint32_t* Qu = (const uint32_t*)Qs;
    const uint32_t* Ku = (const uint32_t*)Ks;
    const uint32_t* Vu = (const uint32_t*)Vt;

    int q0 = blockIdx.x * 128;
    int h  = blockIdx.y;
    int b  = blockIdx.z;
    int tid = threadIdx.x, lane = tid & 31, wid = tid >> 5;
    int lr = lane >> 2, lc = lane & 3;

    size_t head_base = (size_t)(b * NH + h) * S_LEN * HS;
    const float* Qg = g_Q + head_base;
    const float* Kg = g_K + head_base;
    const float* Vg = g_V + head_base;
    const float scale = 0.125f;

    // stage Q (pre-scaled, fp16)
    #pragma unroll
    for (int t = 0; t < 8; t++) {
        int idx = tid + t * 256;
        int m = idx >> 4, c = (idx & 15) * 4;
        float4 v = *(const float4*)(Qg + (size_t)(q0 + m) * HS + c);
        *(__half2*)(Qs + m * QK_PAD + c)     = __floats2half2_rn(v.x * scale, v.y * scale);
        *(__half2*)(Qs + m * QK_PAD + c + 2) = __floats2half2_rn(v.z * scale, v.w * scale);
    }

    float m0s = -1e30f, m1s = -1e30f, l0s = 0.f, l1s = 0.f;
    float oacc[8][4] = {};

    for (int j0 = 0; j0 < S_LEN; j0 += 128) {
        __syncthreads();   // previous tile's reads complete
        // stage K
        #pragma unroll
        for (int t = 0; t < 8; t++) {
            int idx = tid + t * 256;
            int m = idx >> 4, c = (idx & 15) * 4;
            float4 v = *(const float4*)(Kg + (size_t)(j0 + m) * HS + c);
            *(__half2*)(Ks + m * QK_PAD + c)     = __floats2half2_rn(v.x, v.y);
            *(__half2*)(Ks + m * QK_PAD + c + 2) = __floats2half2_rn(v.z, v.w);
        }
        // stage V transposed
        #pragma unroll
        for (int t = 0; t < 8; t++) {
            int idx = tid + t * 256;
            int s = idx >> 4, c4 = (idx & 15) * 4;
            float4 v = *(const float4*)(Vg + (size_t)(j0 + s) * HS + c4);
            Vt[(c4 + 0) * VT_PAD + s] = __float2half_rn(v.x);
            Vt[(c4 + 1) * VT_PAD + s] = __float2half_rn(v.y);
            Vt[(c4 + 2) * VT_PAD + s] = __float2half_rn(v.z);
            Vt[(c4 + 3) * VT_PAD + s] = __float2half_rn(v.w);
        }
        __syncthreads();

        // S = Q K^T  (warp: 16 rows x 128 cols = 16 n-tiles)
        float sacc[16][4] = {};
        int m0 = wid * 16;
        #pragma unroll
        for (int ks = 0; ks < 4; ks++) {
            uint32_t af[4];
            af[0] = Qu[(m0 +     lr) * 36 + ks * 8 +     lc];
            af[1] = Qu[(m0 + 8 + lr) * 36 + ks * 8 +     lc];
            af[2] = Qu[(m0 +     lr) * 36 + ks * 8 + 4 + lc];
            af[3] = Qu[(m0 + 8 + lr) * 36 + ks * 8 + 4 + lc];
            #pragma unroll
            for (int nt = 0; nt < 16; nt++) {
                uint32_t bf[2];
                bf[0] = Ku[(nt * 8 + lr) * 36 + ks * 8 +     lc];
                bf[1] = Ku[(nt * 8 + lr) * 36 + ks * 8 + 4 + lc];
                mma_f16(sacc[nt], af, bf, sacc[nt]);
            }
        }

        // online softmax (row0 = lr, row1 = lr+8; cols within 4-lane group)
        float rm0 = -1e30f, rm1 = -1e30f;
        #pragma unroll
        for (int nt = 0; nt < 16; nt++) {
            rm0 = fmaxf(rm0, fmaxf(sacc[nt][0], sacc[nt][1]));
            rm1 = fmaxf(rm1, fmaxf(sacc[nt][2], sacc[nt][3]));
        }
        rm0 = fmaxf(rm0, __shfl_xor_sync(0xffffffffu, rm0, 1));
        rm0 = fmaxf(rm0, __shfl_xor_sync(0xffffffffu, rm0, 2));
        rm1 = fmaxf(rm1, __shfl_xor_sync(0xffffffffu, rm1, 1));
        rm1 = fmaxf(rm1, __shfl_xor_sync(0xffffffffu, rm1, 2));
        float nm0 = fmaxf(m0s, rm0), nm1 = fmaxf(m1s, rm1);

        float sum0 = 0.f, sum1 = 0.f;
        #pragma unroll
        for (int nt = 0; nt < 16; nt++) {
            sacc[nt][0] = fast_exp(sacc[nt][0] - nm0);
            sacc[nt][1] = fast_exp(sacc[nt][1] - nm0);
            sacc[nt][2] = fast_exp(sacc[nt][2] - nm1);
            sacc[nt][3] = fast_exp(sacc[nt][3] - nm1);
            sum0 += sacc[nt][0] + sacc[nt][1];
            sum1 += sacc[nt][2] + sacc[nt][3];
        }
        sum0 += __shfl_xor_sync(0xffffffffu, sum0, 1);
        sum0 += __shfl_xor_sync(0xffffffffu, sum0, 2);
        sum1 += __shfl_xor_sync(0xffffffffu, sum1, 1);
        sum1 += __shfl_xor_sync(0xffffffffu, sum1, 2);

        float corr0 = fast_exp(m0s - nm0);
        float corr1 = fast_exp(m1s - nm1);
        l0s = l0s * corr0 + sum0;  m0s = nm0;
        l1s = l1s * corr1 + sum1;  m1s = nm1;
        #pragma unroll
        for (int ht = 0; ht < 8; ht++) {
            oacc[ht][0] *= corr0; oacc[ht][1] *= corr0;
            oacc[ht][2] *= corr1; oacc[ht][3] *= corr1;
        }

        // O += P V  (P regs reinterpreted as A fragments)
        #pragma unroll
        for (int kt = 0; kt < 8; kt++) {
            uint32_t pa[4];
            pa[0] = pack_h2(sacc[2 * kt][0],     sacc[2 * kt][1]);
            pa[1] = pack_h2(sacc[2 * kt][2],     sacc[2 * kt][3]);
            pa[2] = pack_h2(sacc[2 * kt + 1][0], sacc[2 * kt + 1][1]);
            pa[3] = pack_h2(sacc[2 * kt + 1][2], sacc[2 * kt + 1][3]);
            #pragma unroll
            for (int ht = 0; ht < 8; ht++) {
                uint32_t bf[2];
                bf[0] = Vu[(ht * 8 + lr) * 68 + kt * 8 +     lc];
                bf[1] = Vu[(ht * 8 + lr) * 68 + kt * 8 + 4 + lc];
                mma_f16(oacc[ht], pa, bf, oacc[ht]);
            }
        }
    }

    // epilogue
    float inv0 = 1.0f / l0s, inv1 = 1.0f / l1s;
    int r0g = q0 + wid * 16 + lr;
    #pragma unroll
    for (int ht = 0; ht < 8; ht++) {
        int col = h * HS + ht * 8 + 2 * lc;
        float2 v0 = { oacc[ht][0] * inv0, oacc[ht][1] * inv0 };
        float2 v1 = { oacc[ht][2] * inv1, oacc[ht][3] * inv1 };
        *(float2*)(g_attn + ((size_t)b * S_LEN + r0g)     * DM + col) = v0;
        *(float2*)(g_attn + ((size_t)b * S_LEN + r0g + 8) * DM + col) = v1;
    }
}

// ---------------------------------------------------------------------------
extern "C" void kernel_launch(void* const* d_in, const int* in_sizes, int n_in,
                              void* d_out, int out_size)
{
    const float* query  = (const float*)d_in[0];
    const float* key_in = (const float*)d_in[1];
    const float* value  = (const float*)d_in[2];
    const float* Wq     = (const float*)d_in[3];
    const float* Wk     = (const float*)d_in[4];
    const float* Wv     = (const float*)d_in[5];
    const float* bq     = (const float*)d_in[6];
    const float* bk     = (const float*)d_in[7];
    const float* bv     = (const float*)d_in[8];
    const float* Wo     = (const float*)d_in[9];
    const float* bo     = (const float*)d_in[10];
    float* out = (float*)d_out;

    cudaFuncSetAttribute(flash_mma_kernel,
                         cudaFuncAttributeMaxDynamicSharedMemorySize,
                         FLASH_SMEM);

    transpose_w_kernel<<<dim3(16, 16, 3), 256>>>(Wq, Wk, Wv);
    qkv_mma_kernel<<<dim3(32, 8, 3), 256>>>(query, key_in, value, bq, bk, bv);
    flash_mma_kernel<<<dim3(S_LEN / 128, NH, NBATCH), 256, FLASH_SMEM>>>();
    oproj_mma_kernel<<<dim3(32, 8), 256>>>(Wo, bo, out);
}